// round 17
// baseline (speedup 1.0000x reference)
#include <cuda_runtime.h>
#include <cuda_fp16.h>
#include <math.h>
#include <stdint.h>

#define DIM 256
#define BATCH 4
#define SEQ 4096
#define M_TOTAL (BATCH * SEQ)

// fp16 scratch (allocation-free rule: device globals)
__device__ __half g_xh[M_TOTAL * DIM];
__device__ __half g_wh[3 * DIM * DIM];
__device__ __half g_qh[M_TOTAL * DIM];
__device__ __half g_kh[M_TOTAL * DIM];
__device__ __half g_vh[M_TOTAL * DIM];

// ---------------------------------------------------------------------------
// Kernel 0: convert x and W to fp16.
// ---------------------------------------------------------------------------
__global__ __launch_bounds__(256) void split_kernel(
    const float* __restrict__ x,
    const float* __restrict__ Wq, const float* __restrict__ Wk,
    const float* __restrict__ Wv)
{
    const int tid = blockIdx.x * blockDim.x + threadIdx.x;
    const int nt  = gridDim.x * blockDim.x;
    for (int i = tid; i < M_TOTAL * DIM / 4; i += nt) {
        float4 v = ((const float4*)x)[i];
        *(half2*)&g_xh[i * 4]     = __halves2half2(__float2half_rn(v.x), __float2half_rn(v.y));
        *(half2*)&g_xh[i * 4 + 2] = __halves2half2(__float2half_rn(v.z), __float2half_rn(v.w));
    }
    const float* Ws[3] = {Wq, Wk, Wv};
#pragma unroll
    for (int s = 0; s < 3; s++) {
        const float4* wp = (const float4*)Ws[s];
        for (int i = tid; i < DIM * DIM / 4; i += nt) {
            float4 v = wp[i];
            __half* o = g_wh + s * DIM * DIM + i * 4;
            *(half2*)(o)     = __halves2half2(__float2half_rn(v.x), __float2half_rn(v.y));
            *(half2*)(o + 2) = __halves2half2(__float2half_rn(v.z), __float2half_rn(v.w));
        }
    }
}

// ---------------------------------------------------------------------------
// Warp-MMA helpers (plain PTX — valid on compute_103)
// ---------------------------------------------------------------------------
__device__ __forceinline__ uint32_t smem_u32(const void* p) {
    return (uint32_t)__cvta_generic_to_shared(p);
}
__device__ __forceinline__ void cp16(uint32_t dst, const void* src) {
    asm volatile("cp.async.cg.shared.global [%0], [%1], 16;\n" :: "r"(dst), "l"(src));
}
__device__ __forceinline__ void ldm4(uint32_t r[4], uint32_t addr) {
    asm volatile("ldmatrix.sync.aligned.m8n8.x4.shared.b16 {%0,%1,%2,%3}, [%4];"
                 : "=r"(r[0]), "=r"(r[1]), "=r"(r[2]), "=r"(r[3]) : "r"(addr));
}
__device__ __forceinline__ void ldm4t(uint32_t r[4], uint32_t addr) {
    asm volatile("ldmatrix.sync.aligned.m8n8.x4.trans.shared.b16 {%0,%1,%2,%3}, [%4];"
                 : "=r"(r[0]), "=r"(r[1]), "=r"(r[2]), "=r"(r[3]) : "r"(addr));
}
__device__ __forceinline__ void mma16(float c[4], const uint32_t a[4],
                                      uint32_t b0, uint32_t b1) {
    asm volatile(
        "mma.sync.aligned.m16n8k16.row.col.f32.f16.f16.f32 "
        "{%0,%1,%2,%3}, {%4,%5,%6,%7}, {%8,%9}, {%0,%1,%2,%3};"
        : "+f"(c[0]), "+f"(c[1]), "+f"(c[2]), "+f"(c[3])
        : "r"(a[0]), "r"(a[1]), "r"(a[2]), "r"(a[3]), "r"(b0), "r"(b1));
}

#define KPB 528     // 256-half row pitch in bytes (+16B pad)
#define PPB 144     // 64-half row pitch in bytes (+16B pad)

// ---------------------------------------------------------------------------
// Kernel 1: QKV projection, single-term fp16 MMA, 128m x 64n CTA tile.
// ---------------------------------------------------------------------------
#define QSM_XH 0
#define QSM_WH (QSM_XH + 128 * KPB)
#define QSMEM_BYTES (QSM_WH + 64 * KPB)   // 101376

extern __shared__ char smem_raw[];

__global__ __launch_bounds__(256, 1) void qkv_mma_kernel(
    const float* __restrict__ bq, const float* __restrict__ bk,
    const float* __restrict__ bv)
{
    const int tid = threadIdx.x;
    const int w = tid >> 5, lane = tid & 31;
    const int g = lane >> 2, tg = lane & 3;
    const int wm = w & 3, wn = w >> 2;
    const int wsel = blockIdx.x >> 2;
    const int n0   = (blockIdx.x & 3) * 64;
    const int m0   = blockIdx.y * 128;
    const float* bias = (wsel == 0) ? bq : (wsel == 1) ? bk : bv;

    const uint32_t sXH = smem_u32(smem_raw + QSM_XH);
    const uint32_t sWH = smem_u32(smem_raw + QSM_WH);

    {
#pragma unroll
        for (int it = 0; it < 16; it++) {
            int idx = it * 256 + tid, row = idx >> 5, u = idx & 31;
            cp16(sXH + (uint32_t)(row * KPB + u * 16),
                 g_xh + (size_t)(m0 + row) * DIM + u * 8);
        }
        const __half* wh = g_wh + (size_t)wsel * DIM * DIM + (size_t)n0 * DIM;
#pragma unroll
        for (int it = 0; it < 8; it++) {
            int idx = it * 256 + tid, row = idx >> 5, u = idx & 31;
            cp16(sWH + (uint32_t)(row * KPB + u * 16), wh + (size_t)row * DIM + u * 8);
        }
    }
    asm volatile("cp.async.commit_group;\n" ::: "memory");
    asm volatile("cp.async.wait_group 0;\n" ::: "memory");
    __syncthreads();

    const int mm = lane >> 3, rr = lane & 7;
    const uint32_t aX0 = sXH + (32 * wm + ((mm & 1) << 3) + rr) * KPB + (mm >> 1) * 16;
    const uint32_t aX1 = aX0 + 16 * KPB;
    const uint32_t bW  = sWH + (32 * wn + ((mm >> 1) << 3) + rr) * KPB + (mm & 1) * 16;

    float c[2][4][4];
#pragma unroll
    for (int m = 0; m < 2; m++)
#pragma unroll
        for (int n = 0; n < 4; n++)
#pragma unroll
            for (int j = 0; j < 4; j++) c[m][n][j] = 0.f;

#pragma unroll 8
    for (int s = 0; s < 16; s++) {
        uint32_t xa[4], xb[4], b0[4], b1[4];
        ldm4(xa, aX0 + s * 32);
        ldm4(xb, aX1 + s * 32);
        ldm4(b0, bW + s * 32);
        ldm4(b1, bW + 16 * KPB + s * 32);
        mma16(c[0][0], xa, b0[0], b0[1]);
        mma16(c[0][1], xa, b0[2], b0[3]);
        mma16(c[0][2], xa, b1[0], b1[1]);
        mma16(c[0][3], xa, b1[2], b1[3]);
        mma16(c[1][0], xb, b0[0], b0[1]);
        mma16(c[1][1], xb, b0[2], b0[3]);
        mma16(c[1][2], xb, b1[0], b1[1]);
        mma16(c[1][3], xb, b1[2], b1[3]);
    }

    __half* dst = (wsel == 0) ? g_qh : (wsel == 1) ? g_kh : g_vh;
    const int colg = n0 + 32 * wn + 2 * tg;
#pragma unroll
    for (int m = 0; m < 2; m++) {
#pragma unroll
        for (int n = 0; n < 4; n++) {
            int col = colg + 8 * n;
            float b0 = bias[col], b1 = bias[col + 1];
#pragma unroll
            for (int h = 0; h < 2; h++) {
                int row = m0 + 32 * wm + 16 * m + g + 8 * h;
                float y0 = c[m][n][2 * h] + b0, y1 = c[m][n][2 * h + 1] + b1;
                *(half2*)&dst[(size_t)row * DIM + col] =
                    __halves2half2(__float2half_rn(y0), __float2half_rn(y1));
            }
        }
    }
}

// ---------------------------------------------------------------------------
// Kernel 2: flash attention — WARP-SPECIALIZED, 256 threads, 8 warps.
//   warps 0-3 (S-warps) : S(t+1) = Q @ K^T for q rows 16w (Q frags register-
//                         resident), softmax -> P buffer (t+1)%2, own l sums.
//   warps 4-7 (PV-warps): O += P(t) @ V(t) for d strip 64*(w-4), O in regs.
//   Each SMSP gets one S-warp + one PV-warp -> LDSM-heavy and MMA-heavy
//   streams overlap structurally (single-CTA phases were serialized).
//   K,V,P double-buffered; cp.async group(t) = {K(t+2), V(t+1)}; 1 sync/tile.
// CTA = (batch, 64 queries); 64-key tiles; 188 KB smem (1 CTA/SM).
// ---------------------------------------------------------------------------
#define TBUF (64 * KPB)                    // 33792
#define PBUF (64 * PPB)                    // 9216
#define SM_QH 0
#define SM_KH (SM_QH + TBUF)               // 2 buffers
#define SM_VH (SM_KH + 2 * TBUF)           // 2 buffers
#define SM_PH (SM_VH + 2 * TBUF)           // 2 buffers
#define SM_LS (SM_PH + 2 * PBUF)
#define SMEM_BYTES (SM_LS + 64 * 4)        // 187648

__global__ __launch_bounds__(256, 1) void attn_mma_kernel(float* __restrict__ out)
{
    const int tid  = threadIdx.x;
    const int w    = tid >> 5;         // 0..7
    const int lane = tid & 31;
    const int g    = lane >> 2;
    const int tg   = lane & 3;
    const bool isS = (w < 4);
    const int sw   = w & 3;            // S: q strip 16*sw ; PV: d strip 64*sw
    const int bb   = blockIdx.y;
    const int q0   = blockIdx.x * 64;
    const size_t qbase = ((size_t)bb * SEQ + q0) * DIM;

    const uint32_t sQH = smem_u32(smem_raw + SM_QH);
    const uint32_t sKH = smem_u32(smem_raw + SM_KH);
    const uint32_t sVH = smem_u32(smem_raw + SM_VH);
    const uint32_t sPH = smem_u32(smem_raw + SM_PH);
    float* Ls = (float*)(smem_raw + SM_LS);

    const int mm = lane >> 3, rr = lane & 7;
    // S-warp addressing
    const uint32_t aQ  = sQH + (16 * sw + ((mm & 1) << 3) + rr) * KPB + (mm >> 1) * 16;
    const uint32_t oK  = (uint32_t)(((mm >> 1 << 3) + rr) * KPB + (mm & 1) * 16);
    // PV-warp addressing (offsets within buffers)
    const uint32_t oP  = (uint32_t)((((mm & 1) << 3) + rr) * PPB + (mm >> 1) * 16);
    const uint32_t oV  = (uint32_t)((((mm & 1) << 3) + rr) * KPB + (mm >> 1) * 16)
                       + (uint32_t)sw * 128;

    const __half* khg = g_kh + ((size_t)bb * SEQ) * DIM;
    const __half* vhg = g_vh + ((size_t)bb * SEQ) * DIM;

    // ---- prologue: {Q, K0->Kbuf0, V0->Vbuf0}, then {K1->Kbuf1} ----
#pragma unroll
    for (int it = 0; it < 8; it++) {
        int idx = it * 256 + tid, row = idx >> 5, u = idx & 31;
        uint32_t so = (uint32_t)(row * KPB + u * 16);
        size_t   go = (size_t)row * DIM + u * 8;
        cp16(sQH + so, g_qh + qbase + go);
        cp16(sKH + so, khg + go);
        cp16(sVH + so, vhg + go);
    }
#pragma unroll
    for (int it = 0; it < 8; it++) {
        int idx = it * 256 + tid, row = idx >> 5, u = idx & 31;
        cp16(sKH + TBUF + (uint32_t)(row * KPB + u * 16),
             khg + (size_t)(64 + row) * DIM + u * 8);
    }
    asm volatile("cp.async.commit_group;\n" ::: "memory");
    asm volatile("cp.async.wait_group 0;\n" ::: "memory");
    __syncthreads();

    const int T = SEQ / 64;
    const float SC = 0.0625f;
    const int rowS = 16 * sw + g;

    uint32_t qf[16][4];          // S-warps only
    float o[4][8][4];            // PV-warps only
    float lr0 = 0.f, lr1 = 0.f;  // S-warps only

    if (isS) {
#pragma unroll
        for (int s = 0; s < 16; s++) ldm4(qf[s], aQ + s * 32);
        // ---- S(0) + softmax(0) -> Pbuf0 ----
        const uint32_t bK = sKH + oK;
        float sc[8][4];
#pragma unroll
        for (int n = 0; n < 8; n++)
#pragma unroll
            for (int j = 0; j < 4; j++) sc[n][j] = 0.f;
#pragma unroll 4
        for (int s = 0; s < 16; s++) {
#pragma unroll
            for (int c = 0; c < 4; c++) {
                uint32_t kb[4];
                ldm4(kb, bK + (uint32_t)(c * 16 * KPB) + s * 32);
                mma16(sc[2 * c],     qf[s], kb[0], kb[1]);
                mma16(sc[2 * c + 1], qf[s], kb[2], kb[3]);
            }
        }
        __half* Pw = (__half*)(smem_raw + SM_PH);
#pragma unroll
        for (int n = 0; n < 8; n++) {
            float p0 = __expf(sc[n][0] * SC);
            float p1 = __expf(sc[n][1] * SC);
            float p2 = __expf(sc[n][2] * SC);
            float p3 = __expf(sc[n][3] * SC);
            lr0 += p0 + p1;  lr1 += p2 + p3;
            *(half2*)&Pw[rowS * 72 + 2 * tg + 8 * n] =
                __halves2half2(__float2half_rn(p0), __float2half_rn(p1));
            *(half2*)&Pw[(rowS + 8) * 72 + 2 * tg + 8 * n] =
                __halves2half2(__float2half_rn(p2), __float2half_rn(p3));
        }
    } else {
#pragma unroll
        for (int m = 0; m < 4; m++)
#pragma unroll
            for (int n = 0; n < 8; n++)
#pragma unroll
                for (int j = 0; j < 4; j++) o[m][n][j] = 0.f;
    }
    __syncthreads();

    // ---- main loop: S-warps do S(t+1); PV-warps do PV(t) ----
    for (int tI = 0; tI < T; tI++) {
        // issue group(t): K(t+2) -> Kbuf[t%2], V(t+1) -> Vbuf[(t+1)%2]
        if (tI + 2 < T) {
            const __half* kp = khg + (size_t)(tI + 2) * 64 * DIM;
            uint32_t kb = sKH + (uint32_t)(tI & 1) * TBUF;
#pragma unroll
            for (int it = 0; it < 8; it++) {
                int idx = it * 256 + tid, row = idx >> 5, u = idx & 31;
                cp16(kb + (uint32_t)(row * KPB + u * 16), kp + (size_t)row * DIM + u * 8);
            }
        }
        if (tI + 1 < T) {
            const __half* vp = vhg + (size_t)(tI + 1) * 64 * DIM;
            uint32_t vb = sVH + (uint32_t)((tI + 1) & 1) * TBUF;
#pragma unroll
            for (int it = 0; it < 8; it++) {
                int idx = it * 256 + tid, row = idx >> 5, u = idx & 31;
                cp16(vb + (uint32_t)(row * KPB + u * 16), vp + (size_t)row * DIM + u * 8);
            }
        }
        asm volatile("cp.async.commit_group;\n" ::: "memory");

        if (isS) {
            if (tI + 1 < T) {
                // ---- S(t+1) from Kbuf[(t+1)%2] ----
                const uint32_t bK = sKH + (uint32_t)((tI + 1) & 1) * TBUF + oK;
                float sc[8][4];
#pragma unroll
                for (int n = 0; n < 8; n++)
#pragma unroll
                    for (int j = 0; j < 4; j++) sc[n][j] = 0.f;
#pragma unroll 4
                for (int s = 0; s < 16; s++) {
#pragma unroll
                    for (int c = 0; c < 4; c++) {
                        uint32_t kb[4];
                        ldm4(kb, bK + (uint32_t)(c * 16 * KPB) + s * 32);
                        mma16(sc[2 * c],     qf[s], kb[0], kb[1]);
                        mma16(sc[2 * c + 1], qf[s], kb[2], kb[3]);
                    }
                }
                __half* Pw = (__half*)(smem_raw + SM_PH + ((tI + 1) & 1) * PBUF);
#pragma unroll
                for (int n = 0; n < 8; n++) {
                    float p0 = __expf(sc[n][0] * SC);
                    float p1 = __expf(sc[n][1] * SC);
                    float p2 = __expf(sc[n][2] * SC);
                    float p3 = __expf(sc[n][3] * SC);
                    lr0 += p0 + p1;  lr1 += p2 + p3;
                    *(half2*)&Pw[rowS * 72 + 2 * tg + 8 * n] =
                        __halves2half2(__float2half_rn(p0), __float2half_rn(p1));
                    *(half2*)&Pw[(rowS + 8) * 72 + 2 * tg + 8 * n] =
                        __halves2half2(__float2half_rn(p2), __float2half_rn(p3));
                }
            }
        } else {
            // ---- PV(t): O += P(t) @ V(t), d strip 64*sw ----
            const uint32_t aP = sPH + (uint32_t)(tI & 1) * PBUF + oP;
            const uint32_t bV = sVH + (uint32_t)(tI & 1) * TBUF + oV;
#pragma unroll
            for (int s = 0; s < 4; s++) {
                uint32_t pa[4][4];
#pragma unroll
                for (int m = 0; m < 4; m++)
                    ldm4(pa[m], aP + (uint32_t)(m * 16 * PPB) + s * 32);
#pragma unroll
                for (int cc = 0; cc < 4; cc++) {
                    uint32_t vb[4];
                    ldm4t(vb, bV + (uint32_t)(s * 16 * KPB) + cc * 32);
#pragma unroll
                    for (int m = 0; m < 4; m++) {
                        mma16(o[m][2 * cc],     pa[m], vb[0], vb[1]);
                        mma16(o[m][2 * cc + 1], pa[m], vb[2], vb[3]);
                    }
                }
            }
        }

        asm volatile("cp.async.wait_group 0;\n" ::: "memory");
        __syncthreads();
    }

    // ---- epilogue ----
    if (isS) {
        lr0 += __shfl_xor_sync(0xffffffffu, lr0, 1);
        lr0 += __shfl_xor_sync(0xffffffffu, lr0, 2);
        lr1 += __shfl_xor_sync(0xffffffffu, lr1, 1);
        lr1 += __shfl_xor_sync(0xffffffffu, lr1, 2);
        if (tg == 0) {
            Ls[rowS]     = lr0;
            Ls[rowS + 8] = lr1;
        }
    }
    __syncthreads();

    if (!isS) {
#pragma unroll
        for (int m = 0; m < 4; m++) {
            const float invA = 1.0f / Ls[16 * m + g];
            const float invB = 1.0f / Ls[16 * m + 8 + g];
            const size_t base = ((size_t)bb * SEQ + q0 + 16 * m + g) * DIM
                              + 64 * sw + 2 * tg;
#pragma unroll
            for (int n = 0; n < 8; n++) {
                float2 vA = make_float2(o[m][n][0] * invA, o[m][n][1] * invA);
                float2 vB = make_float2(o[m][n][2] * invB, o[m][n][3] * invB);
                *(float2*)&out[base + 8 * n]           = vA;
                *(float2*)&out[base + 8 * DIM + 8 * n] = vB;
            }
        }
    }
}

// ---------------------------------------------------------------------------
extern "C" void kernel_launch(void* const* d_in, const int* in_sizes, int n_in,
                              void* d_out, int out_size)
{
    const float* x  = (const float*)d_in[0];
    const float* Wq = (const float*)d_in[1];
    const float* bq = (const float*)d_in[2];
    const float* Wk = (const float*)d_in[3];
    const float* bk = (const float*)d_in[4];
    const float* Wv = (const float*)d_in[5];
    const float* bv = (const float*)d_in[6];
    float* out = (float*)d_out;

    (void)in_sizes; (void)n_in; (void)out_size;

    split_kernel<<<2048, 256>>>(x, Wq, Wk, Wv);

    cudaFuncSetAttribute(qkv_mma_kernel,
                         cudaFuncAttributeMaxDynamicSharedMemorySize, QSMEM_BYTES);
    qkv_mma_kernel<<<dim3(12, 128), 256, QSMEM_BYTES>>>(bq, bk, bv);

    cudaFuncSetAttribute(attn_mma_kernel,
                         cudaFuncAttributeMaxDynamicSharedMemorySize, SMEM_BYTES);
    attn_mma_kernel<<<dim3(SEQ / 64, BATCH), 256, SMEM_BYTES>>>(out);
}